// round 3
// baseline (speedup 1.0000x reference)
#include <cuda_runtime.h>
#include <cuda_bf16.h>
#include <cstdint>

#define NN 50000
#define EE 800000
#define TOT (EE + NN)

// ---------------- scratch (static device globals; no allocations) ----------------
__device__ float g_h[(size_t)NN * 128];          // per-conv GEMM output
__device__ float g_z1[2][(size_t)NN * 128];      // xZ1 (real), xfZ1 (fake)
__device__ float g_as[NN * 2];                   // alpha_src per node per head
__device__ float g_ad[NN * 2];                   // alpha_dst per node per head
__device__ int   g_counts[NN];
__device__ int   g_rowstart[2][NN + 1];
__device__ int   g_cursor[NN];
__device__ int   g_csr[2][TOT];                  // incoming-edge source lists (CSR by dst)

__device__ __forceinline__ float lrelu(float v, float s) { return v > 0.f ? v : s * v; }

// packed fp32x2 FMA (Blackwell): d = a*b + c elementwise on 2-float packs
__device__ __forceinline__ unsigned long long ffma2(unsigned long long a,
                                                    unsigned long long b,
                                                    unsigned long long c) {
    unsigned long long d;
    asm("fma.rn.f32x2 %0, %1, %2, %3;" : "=l"(d) : "l"(a), "l"(b), "l"(c));
    return d;
}
__device__ __forceinline__ unsigned long long pack2(float v) {
    unsigned long long r;
    unsigned int u = __float_as_uint(v);
    asm("mov.b64 %0, {%1, %1};" : "=l"(r) : "r"(u));
    return r;
}

// ---------------- CSR build ----------------
__global__ void hist_kernel(const int* __restrict__ ei) {
    int i = blockIdx.x * blockDim.x + threadIdx.x;
    if (i < EE) atomicAdd(&g_counts[ei[EE + i]], 1);
}

// scan: rowstart include +1 self loop per node; also initializes cursor
__global__ void scan_kernel(int g) {
    __shared__ int part[1024];
    const int tid = threadIdx.x;
    const int chunk = (NN + 1023) / 1024;        // 49
    int s = tid * chunk;
    int e = s + chunk; if (e > NN) e = NN; if (s > NN) s = NN;
    int sum = 0;
    for (int i = s; i < e; i++) sum += g_counts[i] + 1;
    part[tid] = sum;
    __syncthreads();
    for (int off = 1; off < 1024; off <<= 1) {
        int v = (tid >= off) ? part[tid - off] : 0;
        __syncthreads();
        part[tid] += v;
        __syncthreads();
    }
    int base = tid ? part[tid - 1] : 0;
    for (int i = s; i < e; i++) {
        g_rowstart[g][i] = base;
        g_cursor[i] = base;
        base += g_counts[i] + 1;
    }
    if (tid == 1023) g_rowstart[g][NN] = part[1023];
}

__global__ void scatter_kernel(const int* __restrict__ ei, int g) {
    int i = blockIdx.x * blockDim.x + threadIdx.x;
    if (i >= TOT) return;
    int src, dst;
    if (i < EE) { src = ei[i]; dst = ei[EE + i]; }
    else        { src = i - EE; dst = src; }
    int p = atomicAdd(&g_cursor[dst], 1);
    g_csr[g][p] = src;
}

// ---------------- GEMM: O[M,128] = X[M,128] @ W[128,128]  (64x64 tiles, f32x2) ----------------
__global__ void gemm_kernel(const float* __restrict__ X, const float* __restrict__ W,
                            float* __restrict__ O) {
    __shared__ float Ws[128 * 64];
    const int t  = threadIdx.x;                  // 256 threads
    const int tx = t & 7;                        // col group of 8 (0..7)
    const int ty = t >> 3;                       // row pair (0..31)
    const int row0 = blockIdx.x * 64 + ty * 2;
    const int col0 = blockIdx.y * 64;

    {   // stage W[:, col0:col0+64] into smem
        const float4* Wsrc = (const float4*)W;   // row stride = 32 float4
        float4* Wd = (float4*)Ws;
#pragma unroll
        for (int i = 0; i < 8; i++) {
            int idx = t + i * 256;               // 0..2047
            int kr = idx >> 4;                   // k row 0..127
            int c4 = idx & 15;                   // col float4 0..15
            Wd[idx] = Wsrc[kr * 32 + (col0 >> 2) + c4];
        }
    }
    __syncthreads();

    unsigned long long acc0[4], acc1[4];
#pragma unroll
    for (int j = 0; j < 4; j++) { acc0[j] = 0ull; acc1[j] = 0ull; }

    int r0 = row0, r1 = row0 + 1;
    if (r0 >= NN) r0 = NN - 1;
    if (r1 >= NN) r1 = NN - 1;
    const float4* x0p = (const float4*)(X + (size_t)r0 * 128);
    const float4* x1p = (const float4*)(X + (size_t)r1 * 128);

#pragma unroll 4
    for (int k4 = 0; k4 < 32; k4++) {
        float4 a0 = x0p[k4];
        float4 a1 = x1p[k4];
#define GSTEP(KK, E0, E1)                                                          \
        {                                                                          \
            unsigned long long xp0 = pack2(E0);                                    \
            unsigned long long xp1 = pack2(E1);                                    \
            const ulonglong2* wr =                                                 \
                (const ulonglong2*)&Ws[(k4 * 4 + KK) * 64 + tx * 8];               \
            ulonglong2 wA = wr[0];                                                 \
            ulonglong2 wB = wr[1];                                                 \
            acc0[0] = ffma2(xp0, wA.x, acc0[0]);                                   \
            acc0[1] = ffma2(xp0, wA.y, acc0[1]);                                   \
            acc0[2] = ffma2(xp0, wB.x, acc0[2]);                                   \
            acc0[3] = ffma2(xp0, wB.y, acc0[3]);                                   \
            acc1[0] = ffma2(xp1, wA.x, acc1[0]);                                   \
            acc1[1] = ffma2(xp1, wA.y, acc1[1]);                                   \
            acc1[2] = ffma2(xp1, wB.x, acc1[2]);                                   \
            acc1[3] = ffma2(xp1, wB.y, acc1[3]);                                   \
        }
        GSTEP(0, a0.x, a1.x)
        GSTEP(1, a0.y, a1.y)
        GSTEP(2, a0.z, a1.z)
        GSTEP(3, a0.w, a1.w)
#undef GSTEP
    }

    if (row0 < NN) {
        ulonglong2* o = (ulonglong2*)(O + (size_t)row0 * 128 + col0 + tx * 8);
        o[0] = make_ulonglong2(acc0[0], acc0[1]);
        o[1] = make_ulonglong2(acc0[2], acc0[3]);
    }
    if (row0 + 1 < NN) {
        ulonglong2* o = (ulonglong2*)(O + (size_t)(row0 + 1) * 128 + col0 + tx * 8);
        o[0] = make_ulonglong2(acc1[0], acc1[1]);
        o[1] = make_ulonglong2(acc1[2], acc1[3]);
    }
}

// ---------------- alpha_src / alpha_dst: per node per head dot products ----------------
__global__ void alpha_kernel(const float* __restrict__ H,
                             const float* __restrict__ a_src,
                             const float* __restrict__ a_dst) {
    int w = (blockIdx.x * blockDim.x + threadIdx.x) >> 5;
    if (w >= NN) return;
    int lane = threadIdx.x & 31;
    int head = lane >> 4;
    int d0 = (lane & 15) * 4;
    float4 v = *(const float4*)(H + (size_t)w * 128 + lane * 4);
    const float* as = a_src + head * 64 + d0;
    const float* ad = a_dst + head * 64 + d0;
    float s = v.x * as[0] + v.y * as[1] + v.z * as[2] + v.w * as[3];
    float d = v.x * ad[0] + v.y * ad[1] + v.z * ad[2] + v.w * ad[3];
#pragma unroll
    for (int off = 8; off >= 1; off >>= 1) {
        s += __shfl_xor_sync(0xffffffffu, s, off);
        d += __shfl_xor_sync(0xffffffffu, d, off);
    }
    if ((lane & 15) == 0) {
        g_as[w * 2 + head] = s;
        g_ad[w * 2 + head] = d;
    }
}

// ---------------- softmax aggregation: one warp per destination node ----------------
__global__ void agg_kernel(const float* __restrict__ H, int g,
                           const float* __restrict__ bias,
                           float* __restrict__ out, int do_relu) {
    int w = (blockIdx.x * blockDim.x + threadIdx.x) >> 5;
    if (w >= NN) return;
    int lane = threadIdx.x & 31;
    int beg = g_rowstart[g][w], end = g_rowstart[g][w + 1];
    float ad0 = g_ad[w * 2], ad1 = g_ad[w * 2 + 1];

    // online softmax stats (m, s) per head
    float m0 = -1e30f, m1 = -1e30f, s0 = 0.f, s1 = 0.f;
    for (int e = beg + lane; e < end; e += 32) {
        int src = g_csr[g][e];
        float2 av = *(const float2*)&g_as[src * 2];
        float e0 = lrelu(av.x + ad0, 0.2f);
        float e1 = lrelu(av.y + ad1, 0.2f);
        if (e0 > m0) { s0 = s0 * __expf(m0 - e0) + 1.f; m0 = e0; } else s0 += __expf(e0 - m0);
        if (e1 > m1) { s1 = s1 * __expf(m1 - e1) + 1.f; m1 = e1; } else s1 += __expf(e1 - m1);
    }
#pragma unroll
    for (int off = 16; off >= 1; off >>= 1) {
        float mo = __shfl_xor_sync(0xffffffffu, m0, off);
        float so = __shfl_xor_sync(0xffffffffu, s0, off);
        float mn = fmaxf(m0, mo);
        s0 = s0 * __expf(m0 - mn) + so * __expf(mo - mn); m0 = mn;
        mo = __shfl_xor_sync(0xffffffffu, m1, off);
        so = __shfl_xor_sync(0xffffffffu, s1, off);
        mn = fmaxf(m1, mo);
        s1 = s1 * __expf(m1 - mn) + so * __expf(mo - mn); m1 = mn;
    }
    float inv0 = 1.f / s0;
    float inv1 = 1.f / s1;

    const int col  = lane * 4;
    const int head = lane >> 4;
    float4 acc = make_float4(0.f, 0.f, 0.f, 0.f);

    for (int base = beg; base < end; base += 32) {
        int cnt = end - base; if (cnt > 32) cnt = 32;
        int   sidx = 0; float aa0 = 0.f, aa1 = 0.f;
        if (lane < cnt) {
            sidx = g_csr[g][base + lane];
            float2 av = *(const float2*)&g_as[sidx * 2];
            float e0 = lrelu(av.x + ad0, 0.2f);
            float e1 = lrelu(av.y + ad1, 0.2f);
            aa0 = __expf(e0 - m0) * inv0;
            aa1 = __expf(e1 - m1) * inv1;
        }
#pragma unroll 4
        for (int j = 0; j < cnt; j++) {
            int   sj  = __shfl_sync(0xffffffffu, sidx, j);
            float a0j = __shfl_sync(0xffffffffu, aa0, j);
            float a1j = __shfl_sync(0xffffffffu, aa1, j);
            float aj  = head ? a1j : a0j;
            float4 v = *(const float4*)(H + (size_t)sj * 128 + col);
            acc.x += aj * v.x; acc.y += aj * v.y; acc.z += aj * v.z; acc.w += aj * v.w;
        }
    }

    float4 bv = *(const float4*)(bias + col);
    float4 r = make_float4(acc.x + bv.x, acc.y + bv.y, acc.z + bv.z, acc.w + bv.w);
    if (do_relu) {
        r.x = fmaxf(r.x, 0.f); r.y = fmaxf(r.y, 0.f);
        r.z = fmaxf(r.z, 0.f); r.w = fmaxf(r.w, 0.f);
    }
    *(float4*)(out + (size_t)w * 128 + col) = r;
}

// ---------------- tprob = leaky_relu(xZ2 @ Wp + bp, 0.01) ----------------
__global__ void tprob_kernel(const float* __restrict__ Z, const float* __restrict__ Wp,
                             const float* __restrict__ bp, float* __restrict__ out) {
    int w = (blockIdx.x * blockDim.x + threadIdx.x) >> 5;
    if (w >= NN) return;
    int lane = threadIdx.x & 31;
    int col = lane * 4;
    float4 v  = *(const float4*)(Z + (size_t)w * 128 + col);
    float4 p0 = *(const float4*)(Wp + col * 2);
    float4 p1 = *(const float4*)(Wp + col * 2 + 4);
    float a0 = v.x * p0.x + v.y * p0.z + v.z * p1.x + v.w * p1.z;
    float a1 = v.x * p0.y + v.y * p0.w + v.z * p1.y + v.w * p1.w;
#pragma unroll
    for (int off = 16; off >= 1; off >>= 1) {
        a0 += __shfl_xor_sync(0xffffffffu, a0, off);
        a1 += __shfl_xor_sync(0xffffffffu, a1, off);
    }
    if (lane == 0) {
        float o0 = lrelu(a0 + bp[0], 0.01f);
        float o1 = lrelu(a1 + bp[1], 0.01f);
        *(float2*)(out + (size_t)w * 2) = make_float2(o0, o1);
    }
}

// ---------------- fused y heads: blockIdx.y picks one of 4 (Z, idx, Wy) combos ----------------
__global__ void heads_kernel(const float* __restrict__ Z0, const float* __restrict__ Z1,
                             const int* __restrict__ treat, const int* __restrict__ control,
                             const float* __restrict__ WyS, const float* __restrict__ byS,
                             const float* __restrict__ Wy1, const float* __restrict__ by1,
                             const float* __restrict__ Wy0, const float* __restrict__ by0,
                             float* __restrict__ out, int nt, int nc) {
    __shared__ float Ws[128 * 64];
    __shared__ float bs[64];
    __shared__ float wy[64];
    __shared__ float byv;

    const int y = blockIdx.y;
    const float* Z   = (y == 0 || y == 2) ? Z0 : Z1;
    const int*   idx = (y < 2) ? treat : control;
    const float* Wy  = (y == 0 || y == 3) ? Wy1 : Wy0;
    const float* by  = (y == 0 || y == 3) ? by1 : by0;
    const int    cnt = (y < 2) ? nt : nc;
    float* yout = out + (y == 0 ? 0 : y == 1 ? nt : y == 2 ? 2 * nt : 2 * nt + nc);

    const int t = threadIdx.x;                   // 256 threads = 8 warps
#pragma unroll
    for (int i = 0; i < 32; i++) Ws[t + i * 256] = WyS[t + i * 256];
    if (t < 64) { bs[t] = byS[t]; wy[t] = Wy[t]; }
    if (t == 0) byv = by[0];
    __syncthreads();

    const int warp = t >> 5, lane = t & 31;
    for (int i = blockIdx.x * 8 + warp; i < cnt; i += gridDim.x * 8) {
        int node = idx[i];
        const float* z = Z + (size_t)node * 128;
        float za = z[lane], zb = z[lane + 32], zc = z[lane + 64], zd = z[lane + 96];
        float s0 = bs[lane], s1 = bs[lane + 32];
#pragma unroll
        for (int k = 0; k < 128; k++) {
            float src = (k < 32) ? za : (k < 64) ? zb : (k < 96) ? zc : zd;
            float zk = __shfl_sync(0xffffffffu, src, k & 31);
            s0 += zk * Ws[k * 64 + lane];
            s1 += zk * Ws[k * 64 + lane + 32];
        }
        s0 = lrelu(s0, 0.01f);
        s1 = lrelu(s1, 0.01f);
        float p = s0 * wy[lane] + s1 * wy[lane + 32];
#pragma unroll
        for (int off = 16; off >= 1; off >>= 1) p += __shfl_xor_sync(0xffffffffu, p, off);
        if (lane == 0) yout[i] = lrelu(p + byv, 0.01f);
    }
}

// ---------------- launch ----------------
static void build_csr(const int* ei, int g, int* counts_ptr) {
    cudaMemsetAsync(counts_ptr, 0, NN * sizeof(int));
    hist_kernel<<<(EE + 255) / 256, 256>>>(ei);
    scan_kernel<<<1, 1024>>>(g);
    scatter_kernel<<<(TOT + 255) / 256, 256>>>(ei, g);
}

static void run_conv(const float* Xin, const float* W, const float* asrc, const float* adst,
                     const float* bias, int g, float* outp, int do_relu, float* hbuf) {
    gemm_kernel<<<dim3((NN + 63) / 64, 2), 256>>>(Xin, W, hbuf);
    alpha_kernel<<<(NN * 32) / 256, 256>>>(hbuf, asrc, adst);
    agg_kernel<<<(NN * 32) / 256, 256>>>(hbuf, g, bias, outp, do_relu);
}

extern "C" void kernel_launch(void* const* d_in, const int* in_sizes, int n_in,
                              void* d_out, int out_size) {
    const float* x       = (const float*)d_in[0];
    const int*   ei      = (const int*)d_in[1];
    const float* fx      = (const float*)d_in[2];
    const int*   fei     = (const int*)d_in[3];
    const int*   treat   = (const int*)d_in[4];
    const int*   control = (const int*)d_in[5];
    const float* W1      = (const float*)d_in[6];
    const float* as1     = (const float*)d_in[7];
    const float* ad1     = (const float*)d_in[8];
    const float* b1      = (const float*)d_in[9];
    const float* W2      = (const float*)d_in[10];
    const float* as2     = (const float*)d_in[11];
    const float* ad2     = (const float*)d_in[12];
    const float* b2      = (const float*)d_in[13];
    const float* WyS     = (const float*)d_in[14];
    const float* byS     = (const float*)d_in[15];
    const float* Wy1     = (const float*)d_in[16];
    const float* by1     = (const float*)d_in[17];
    const float* Wy0     = (const float*)d_in[18];
    const float* by0     = (const float*)d_in[19];
    const float* Wp      = (const float*)d_in[20];
    const float* bp      = (const float*)d_in[21];
    float* out = (float*)d_out;
    const int nt = in_sizes[4];
    const int nc = in_sizes[5];

    float* hbuf = nullptr;
    float* z1   = nullptr;
    int*   counts_ptr = nullptr;
    cudaGetSymbolAddress((void**)&hbuf, g_h);
    cudaGetSymbolAddress((void**)&z1, g_z1);
    cudaGetSymbolAddress((void**)&counts_ptr, g_counts);
    float* z1a = z1;
    float* z1b = z1 + (size_t)NN * 128;

    const size_t OFF_XZ2  = (size_t)2 * nt + (size_t)2 * nc;
    const size_t OFF_XFZ2 = OFF_XZ2 + (size_t)NN * 128;
    const size_t OFF_TP   = OFF_XFZ2 + (size_t)NN * 128;

    build_csr(ei, 0, counts_ptr);
    build_csr(fei, 1, counts_ptr);

    run_conv(x,   W1, as1, ad1, b1, 0, z1a, 1, hbuf);
    run_conv(fx,  W1, as1, ad1, b1, 1, z1b, 1, hbuf);
    run_conv(z1a, W2, as2, ad2, b2, 0, out + OFF_XZ2,  0, hbuf);
    run_conv(z1b, W2, as2, ad2, b2, 1, out + OFF_XFZ2, 0, hbuf);

    tprob_kernel<<<(NN * 32) / 256, 256>>>(out + OFF_XZ2, Wp, bp, out + OFF_TP);

    heads_kernel<<<dim3(32, 4), 256>>>(out + OFF_XZ2, out + OFF_XFZ2, treat, control,
                                       WyS, byS, Wy1, by1, Wy0, by0, out, nt, nc);
}

// round 4
// speedup vs baseline: 1.5089x; 1.5089x over previous
#include <cuda_runtime.h>
#include <cuda_bf16.h>
#include <cstdint>

#define NN 50000
#define EE 800000
#define TOT (EE + NN)

// ---------------- scratch (static device globals; no allocations) ----------------
__device__ float g_h[2][(size_t)NN * 128];       // per-chain GEMM output
__device__ float g_z1[2][(size_t)NN * 128];      // xZ1 (real), xfZ1 (fake)
__device__ float g_as[2][NN * 2];                // alpha_src per node per head
__device__ float g_ad[2][NN * 2];                // alpha_dst per node per head
__device__ int   g_counts[2][NN];
__device__ int   g_rowstart[2][NN + 1];
__device__ int   g_cursor[2][NN];
__device__ int   g_csr[2][TOT];                  // incoming-edge source lists (CSR by dst)

__device__ __forceinline__ float lrelu(float v, float s) { return v > 0.f ? v : s * v; }

// ---------------- CSR build ----------------
__global__ void hist_kernel(const int* __restrict__ ei, int g) {
    int i = blockIdx.x * blockDim.x + threadIdx.x;
    if (i < EE) atomicAdd(&g_counts[g][ei[EE + i]], 1);
}

// scan: rowstart includes +1 self loop per node; also initializes cursor
__global__ void scan_kernel(int g) {
    __shared__ int part[1024];
    const int tid = threadIdx.x;
    const int chunk = (NN + 1023) / 1024;        // 49
    int s = tid * chunk;
    int e = s + chunk; if (e > NN) e = NN; if (s > NN) s = NN;
    int sum = 0;
    for (int i = s; i < e; i++) sum += g_counts[g][i] + 1;
    part[tid] = sum;
    __syncthreads();
    for (int off = 1; off < 1024; off <<= 1) {
        int v = (tid >= off) ? part[tid - off] : 0;
        __syncthreads();
        part[tid] += v;
        __syncthreads();
    }
    int base = tid ? part[tid - 1] : 0;
    for (int i = s; i < e; i++) {
        g_rowstart[g][i] = base;
        g_cursor[g][i] = base;
        base += g_counts[g][i] + 1;
    }
    if (tid == 1023) g_rowstart[g][NN] = part[1023];
}

__global__ void scatter_kernel(const int* __restrict__ ei, int g) {
    int i = blockIdx.x * blockDim.x + threadIdx.x;
    if (i >= TOT) return;
    int src, dst;
    if (i < EE) { src = ei[i]; dst = ei[EE + i]; }
    else        { src = i - EE; dst = src; }
    int p = atomicAdd(&g_cursor[g][dst], 1);
    g_csr[g][p] = src;
}

// ---------------- GEMM: O[M,128] = X[M,128] @ W[128,128]  (64x64 tiles) ----------------
__global__ void gemm_kernel(const float* __restrict__ X, const float* __restrict__ W,
                            float* __restrict__ O) {
    __shared__ float Ws[128 * 64];
    const int t  = threadIdx.x;                  // 256 threads
    const int tx = t & 15, ty = t >> 4;
    const int row0 = blockIdx.x * 64;
    const int col0 = blockIdx.y * 64;

    {   // stage W[:, col0:col0+64] into smem
        const float4* Wsrc = (const float4*)W;   // row stride = 32 float4
        float4* Wd = (float4*)Ws;
#pragma unroll
        for (int i = 0; i < 8; i++) {
            int idx = t + i * 256;               // 0..2047
            int kr = idx >> 4;                   // k row 0..127
            int c4 = idx & 15;                   // col float4 0..15
            Wd[idx] = Wsrc[kr * 32 + (col0 >> 2) + c4];
        }
    }
    __syncthreads();

    float acc[4][4];
#pragma unroll
    for (int r = 0; r < 4; r++)
#pragma unroll
        for (int c = 0; c < 4; c++) acc[r][c] = 0.f;

    const float* xrow[4];
#pragma unroll
    for (int r = 0; r < 4; r++) {
        int row = row0 + ty * 4 + r;
        if (row >= NN) row = NN - 1;             // clamp (stores are guarded)
        xrow[r] = X + (size_t)row * 128;
    }

#pragma unroll 4
    for (int k = 0; k < 128; k += 4) {
        float xv[4][4];
#pragma unroll
        for (int r = 0; r < 4; r++) {
            float4 v = *(const float4*)(xrow[r] + k);
            xv[r][0] = v.x; xv[r][1] = v.y; xv[r][2] = v.z; xv[r][3] = v.w;
        }
#pragma unroll
        for (int kk = 0; kk < 4; kk++) {
            float4 wv = *(const float4*)&Ws[(k + kk) * 64 + tx * 4];
            float wc0 = wv.x, wc1 = wv.y, wc2 = wv.z, wc3 = wv.w;
#pragma unroll
            for (int r = 0; r < 4; r++) {
                float xr = xv[r][kk];
                acc[r][0] += xr * wc0;
                acc[r][1] += xr * wc1;
                acc[r][2] += xr * wc2;
                acc[r][3] += xr * wc3;
            }
        }
    }

#pragma unroll
    for (int r = 0; r < 4; r++) {
        int row = row0 + ty * 4 + r;
        if (row < NN) {
            float4 o = make_float4(acc[r][0], acc[r][1], acc[r][2], acc[r][3]);
            *(float4*)(O + (size_t)row * 128 + col0 + tx * 4) = o;
        }
    }
}

// ---------------- alpha_src / alpha_dst: per node per head dot products ----------------
__global__ void alpha_kernel(const float* __restrict__ H, int g,
                             const float* __restrict__ a_src,
                             const float* __restrict__ a_dst) {
    int w = (blockIdx.x * blockDim.x + threadIdx.x) >> 5;
    if (w >= NN) return;
    int lane = threadIdx.x & 31;
    int head = lane >> 4;
    int d0 = (lane & 15) * 4;
    float4 v = *(const float4*)(H + (size_t)w * 128 + lane * 4);
    const float* as = a_src + head * 64 + d0;
    const float* ad = a_dst + head * 64 + d0;
    float s = v.x * as[0] + v.y * as[1] + v.z * as[2] + v.w * as[3];
    float d = v.x * ad[0] + v.y * ad[1] + v.z * ad[2] + v.w * ad[3];
#pragma unroll
    for (int off = 8; off >= 1; off >>= 1) {
        s += __shfl_xor_sync(0xffffffffu, s, off);
        d += __shfl_xor_sync(0xffffffffu, d, off);
    }
    if ((lane & 15) == 0) {
        g_as[g][w * 2 + head] = s;
        g_ad[g][w * 2 + head] = d;
    }
}

// ---------------- softmax aggregation: one warp per destination node ----------------
__global__ void agg_kernel(const float* __restrict__ H, int g,
                           const float* __restrict__ bias,
                           float* __restrict__ out, int do_relu) {
    int w = (blockIdx.x * blockDim.x + threadIdx.x) >> 5;
    if (w >= NN) return;
    int lane = threadIdx.x & 31;
    int beg = g_rowstart[g][w], end = g_rowstart[g][w + 1];
    float ad0 = g_ad[g][w * 2], ad1 = g_ad[g][w * 2 + 1];

    // online softmax stats (m, s) per head
    float m0 = -1e30f, m1 = -1e30f, s0 = 0.f, s1 = 0.f;
    for (int e = beg + lane; e < end; e += 32) {
        int src = g_csr[g][e];
        float2 av = *(const float2*)&g_as[g][src * 2];
        float e0 = lrelu(av.x + ad0, 0.2f);
        float e1 = lrelu(av.y + ad1, 0.2f);
        if (e0 > m0) { s0 = s0 * __expf(m0 - e0) + 1.f; m0 = e0; } else s0 += __expf(e0 - m0);
        if (e1 > m1) { s1 = s1 * __expf(m1 - e1) + 1.f; m1 = e1; } else s1 += __expf(e1 - m1);
    }
#pragma unroll
    for (int off = 16; off >= 1; off >>= 1) {
        float mo = __shfl_xor_sync(0xffffffffu, m0, off);
        float so = __shfl_xor_sync(0xffffffffu, s0, off);
        float mn = fmaxf(m0, mo);
        s0 = s0 * __expf(m0 - mn) + so * __expf(mo - mn); m0 = mn;
        mo = __shfl_xor_sync(0xffffffffu, m1, off);
        so = __shfl_xor_sync(0xffffffffu, s1, off);
        mn = fmaxf(m1, mo);
        s1 = s1 * __expf(m1 - mn) + so * __expf(mo - mn); m1 = mn;
    }
    float inv0 = 1.f / s0;
    float inv1 = 1.f / s1;

    const int col  = lane * 4;
    const int head = lane >> 4;
    float4 acc = make_float4(0.f, 0.f, 0.f, 0.f);

    for (int base = beg; base < end; base += 32) {
        int cnt = end - base; if (cnt > 32) cnt = 32;
        int   sidx = 0; float aa0 = 0.f, aa1 = 0.f;
        if (lane < cnt) {
            sidx = g_csr[g][base + lane];
            float2 av = *(const float2*)&g_as[g][sidx * 2];
            float e0 = lrelu(av.x + ad0, 0.2f);
            float e1 = lrelu(av.y + ad1, 0.2f);
            aa0 = __expf(e0 - m0) * inv0;
            aa1 = __expf(e1 - m1) * inv1;
        }
#pragma unroll 4
        for (int j = 0; j < cnt; j++) {
            int   sj  = __shfl_sync(0xffffffffu, sidx, j);
            float a0j = __shfl_sync(0xffffffffu, aa0, j);
            float a1j = __shfl_sync(0xffffffffu, aa1, j);
            float aj  = head ? a1j : a0j;
            float4 v = *(const float4*)(H + (size_t)sj * 128 + col);
            acc.x += aj * v.x; acc.y += aj * v.y; acc.z += aj * v.z; acc.w += aj * v.w;
        }
    }

    float4 bv = *(const float4*)(bias + col);
    float4 r = make_float4(acc.x + bv.x, acc.y + bv.y, acc.z + bv.z, acc.w + bv.w);
    if (do_relu) {
        r.x = fmaxf(r.x, 0.f); r.y = fmaxf(r.y, 0.f);
        r.z = fmaxf(r.z, 0.f); r.w = fmaxf(r.w, 0.f);
    }
    *(float4*)(out + (size_t)w * 128 + col) = r;
}

// ---------------- tprob = leaky_relu(xZ2 @ Wp + bp, 0.01) ----------------
__global__ void tprob_kernel(const float* __restrict__ Z, const float* __restrict__ Wp,
                             const float* __restrict__ bp, float* __restrict__ out) {
    int w = (blockIdx.x * blockDim.x + threadIdx.x) >> 5;
    if (w >= NN) return;
    int lane = threadIdx.x & 31;
    int col = lane * 4;
    float4 v  = *(const float4*)(Z + (size_t)w * 128 + col);
    float4 p0 = *(const float4*)(Wp + col * 2);
    float4 p1 = *(const float4*)(Wp + col * 2 + 4);
    float a0 = v.x * p0.x + v.y * p0.z + v.z * p1.x + v.w * p1.z;
    float a1 = v.x * p0.y + v.y * p0.w + v.z * p1.y + v.w * p1.w;
#pragma unroll
    for (int off = 16; off >= 1; off >>= 1) {
        a0 += __shfl_xor_sync(0xffffffffu, a0, off);
        a1 += __shfl_xor_sync(0xffffffffu, a1, off);
    }
    if (lane == 0) {
        float o0 = lrelu(a0 + bp[0], 0.01f);
        float o1 = lrelu(a1 + bp[1], 0.01f);
        *(float2*)(out + (size_t)w * 2) = make_float2(o0, o1);
    }
}

// ---------------- fused y heads: blockIdx.y picks one of 4 (Z, idx, Wy) combos ----------------
__global__ void heads_kernel(const float* __restrict__ Z0, const float* __restrict__ Z1,
                             const int* __restrict__ treat, const int* __restrict__ control,
                             const float* __restrict__ WyS, const float* __restrict__ byS,
                             const float* __restrict__ Wy1, const float* __restrict__ by1,
                             const float* __restrict__ Wy0, const float* __restrict__ by0,
                             float* __restrict__ out, int nt, int nc) {
    __shared__ float Ws[128 * 64];
    __shared__ float bs[64];
    __shared__ float wy[64];
    __shared__ float byv;

    const int y = blockIdx.y;
    const float* Z   = (y == 0 || y == 2) ? Z0 : Z1;
    const int*   idx = (y < 2) ? treat : control;
    const float* Wy  = (y == 0 || y == 3) ? Wy1 : Wy0;
    const float* by  = (y == 0 || y == 3) ? by1 : by0;
    const int    cnt = (y < 2) ? nt : nc;
    float* yout = out + (y == 0 ? 0 : y == 1 ? nt : y == 2 ? 2 * nt : 2 * nt + nc);

    const int t = threadIdx.x;                   // 256 threads = 8 warps
#pragma unroll
    for (int i = 0; i < 32; i++) Ws[t + i * 256] = WyS[t + i * 256];
    if (t < 64) { bs[t] = byS[t]; wy[t] = Wy[t]; }
    if (t == 0) byv = by[0];
    __syncthreads();

    const int warp = t >> 5, lane = t & 31;
    for (int i = blockIdx.x * 8 + warp; i < cnt; i += gridDim.x * 8) {
        int node = idx[i];
        const float* z = Z + (size_t)node * 128;
        float za = z[lane], zb = z[lane + 32], zc = z[lane + 64], zd = z[lane + 96];
        float s0 = bs[lane], s1 = bs[lane + 32];
#pragma unroll
        for (int k = 0; k < 128; k++) {
            float src = (k < 32) ? za : (k < 64) ? zb : (k < 96) ? zc : zd;
            float zk = __shfl_sync(0xffffffffu, src, k & 31);
            s0 += zk * Ws[k * 64 + lane];
            s1 += zk * Ws[k * 64 + lane + 32];
        }
        s0 = lrelu(s0, 0.01f);
        s1 = lrelu(s1, 0.01f);
        float p = s0 * wy[lane] + s1 * wy[lane + 32];
#pragma unroll
        for (int off = 16; off >= 1; off >>= 1) p += __shfl_xor_sync(0xffffffffu, p, off);
        if (lane == 0) yout[i] = lrelu(p + byv, 0.01f);
    }
}

// ---------------- launch ----------------
static void build_csr(cudaStream_t s, const int* ei, int g, int* counts_ptr) {
    cudaMemsetAsync(counts_ptr, 0, NN * sizeof(int), s);
    hist_kernel<<<(EE + 255) / 256, 256, 0, s>>>(ei, g);
    scan_kernel<<<1, 1024, 0, s>>>(g);
    scatter_kernel<<<(TOT + 255) / 256, 256, 0, s>>>(ei, g);
}

static void run_conv(cudaStream_t s, const float* Xin, const float* W,
                     const float* asrc, const float* adst,
                     const float* bias, int g, float* outp, int do_relu, float* hbuf) {
    gemm_kernel<<<dim3((NN + 63) / 64, 2), 256, 0, s>>>(Xin, W, hbuf);
    alpha_kernel<<<(NN * 32) / 256, 256, 0, s>>>(hbuf, g, asrc, adst);
    agg_kernel<<<(NN * 32) / 256, 256, 0, s>>>(hbuf, g, bias, outp, do_relu);
}

extern "C" void kernel_launch(void* const* d_in, const int* in_sizes, int n_in,
                              void* d_out, int out_size) {
    const float* x       = (const float*)d_in[0];
    const int*   ei      = (const int*)d_in[1];
    const float* fx      = (const float*)d_in[2];
    const int*   fei     = (const int*)d_in[3];
    const int*   treat   = (const int*)d_in[4];
    const int*   control = (const int*)d_in[5];
    const float* W1      = (const float*)d_in[6];
    const float* as1     = (const float*)d_in[7];
    const float* ad1     = (const float*)d_in[8];
    const float* b1      = (const float*)d_in[9];
    const float* W2      = (const float*)d_in[10];
    const float* as2     = (const float*)d_in[11];
    const float* ad2     = (const float*)d_in[12];
    const float* b2      = (const float*)d_in[13];
    const float* WyS     = (const float*)d_in[14];
    const float* byS     = (const float*)d_in[15];
    const float* Wy1     = (const float*)d_in[16];
    const float* by1     = (const float*)d_in[17];
    const float* Wy0     = (const float*)d_in[18];
    const float* by0     = (const float*)d_in[19];
    const float* Wp      = (const float*)d_in[20];
    const float* bp      = (const float*)d_in[21];
    float* out = (float*)d_out;
    const int nt = in_sizes[4];
    const int nc = in_sizes[5];

    float* hbase  = nullptr;
    float* z1     = nullptr;
    int*   counts = nullptr;
    cudaGetSymbolAddress((void**)&hbase, g_h);
    cudaGetSymbolAddress((void**)&z1, g_z1);
    cudaGetSymbolAddress((void**)&counts, g_counts);
    float* hA  = hbase;
    float* hB  = hbase + (size_t)NN * 128;
    float* z1a = z1;
    float* z1b = z1 + (size_t)NN * 128;
    int* cntA = counts;
    int* cntB = counts + NN;

    const size_t OFF_XZ2  = (size_t)2 * nt + (size_t)2 * nc;
    const size_t OFF_XFZ2 = OFF_XZ2 + (size_t)NN * 128;
    const size_t OFF_TP   = OFF_XFZ2 + (size_t)NN * 128;

    // side stream + fork/join events (created once; host-side only, no device mem)
    static cudaStream_t sB = nullptr;
    static cudaEvent_t evFork = nullptr, evJoin = nullptr;
    if (sB == nullptr) {
        cudaStreamCreateWithFlags(&sB, cudaStreamNonBlocking);
        cudaEventCreateWithFlags(&evFork, cudaEventDisableTiming);
        cudaEventCreateWithFlags(&evJoin, cudaEventDisableTiming);
    }
    cudaStream_t sA = 0;  // legacy default (the captured stream)

    // fork
    cudaEventRecord(evFork, sA);
    cudaStreamWaitEvent(sB, evFork, 0);

    // real chain on sA
    build_csr(sA, ei, 0, cntA);
    run_conv(sA, x,   W1, as1, ad1, b1, 0, z1a, 1, hA);
    run_conv(sA, z1a, W2, as2, ad2, b2, 0, out + OFF_XZ2,  0, hA);
    tprob_kernel<<<(NN * 32) / 256, 256, 0, sA>>>(out + OFF_XZ2, Wp, bp, out + OFF_TP);

    // fake chain on sB
    build_csr(sB, fei, 1, cntB);
    run_conv(sB, fx,  W1, as1, ad1, b1, 1, z1b, 1, hB);
    run_conv(sB, z1b, W2, as2, ad2, b2, 1, out + OFF_XFZ2, 0, hB);

    // join
    cudaEventRecord(evJoin, sB);
    cudaStreamWaitEvent(sA, evJoin, 0);

    heads_kernel<<<dim3(32, 4), 256, 0, sA>>>(out + OFF_XZ2, out + OFF_XFZ2, treat, control,
                                              WyS, byS, Wy1, by1, Wy0, by0, out, nt, nc);
}

// round 5
// speedup vs baseline: 1.6353x; 1.0838x over previous
#include <cuda_runtime.h>
#include <cuda_bf16.h>
#include <cstdint>

#define NN 50000
#define EE 800000
#define TOT (EE + NN)

// ---------------- scratch (static device globals; no allocations) ----------------
__device__ float g_h[2][(size_t)NN * 128];       // per-chain GEMM output
__device__ float g_z1[2][(size_t)NN * 128];      // xZ1 (real), xfZ1 (fake)
__device__ float g_as[2][NN * 2];                // alpha_src per node per head
__device__ float g_ad[2][NN * 2];                // alpha_dst per node per head
__device__ int   g_counts[2][NN];
__device__ int   g_rowstart[2][NN + 1];
__device__ int   g_cursor[2][NN];
__device__ int   g_csr[2][TOT];                  // incoming-edge source lists (CSR by dst)

__device__ __forceinline__ float lrelu(float v, float s) { return v > 0.f ? v : s * v; }

__device__ __forceinline__ uint32_t to_tf32(float f) {
    uint32_t r;
    asm("cvt.rna.tf32.f32 %0, %1;" : "=r"(r) : "f"(f));
    return r;
}

__device__ __forceinline__ void mma_tf32(float* d, const uint32_t* a, const uint32_t* b) {
    asm volatile(
        "mma.sync.aligned.m16n8k8.row.col.f32.tf32.tf32.f32 "
        "{%0,%1,%2,%3}, {%4,%5,%6,%7}, {%8,%9}, {%0,%1,%2,%3};\n"
        : "+f"(d[0]), "+f"(d[1]), "+f"(d[2]), "+f"(d[3])
        : "r"(a[0]), "r"(a[1]), "r"(a[2]), "r"(a[3]), "r"(b[0]), "r"(b[1]));
}

// ---------------- CSR build ----------------
__global__ void hist_kernel(const int* __restrict__ ei, int g) {
    int i = blockIdx.x * blockDim.x + threadIdx.x;
    if (i < EE) atomicAdd(&g_counts[g][ei[EE + i]], 1);
}

// scan: rowstart includes +1 self loop per node; also initializes cursor
__global__ void scan_kernel(int g) {
    __shared__ int part[1024];
    const int tid = threadIdx.x;
    const int chunk = (NN + 1023) / 1024;        // 49
    int s = tid * chunk;
    int e = s + chunk; if (e > NN) e = NN; if (s > NN) s = NN;
    int sum = 0;
    for (int i = s; i < e; i++) sum += g_counts[g][i] + 1;
    part[tid] = sum;
    __syncthreads();
    for (int off = 1; off < 1024; off <<= 1) {
        int v = (tid >= off) ? part[tid - off] : 0;
        __syncthreads();
        part[tid] += v;
        __syncthreads();
    }
    int base = tid ? part[tid - 1] : 0;
    for (int i = s; i < e; i++) {
        g_rowstart[g][i] = base;
        g_cursor[g][i] = base;
        base += g_counts[g][i] + 1;
    }
    if (tid == 1023) g_rowstart[g][NN] = part[1023];
}

__global__ void scatter_kernel(const int* __restrict__ ei, int g) {
    int i = blockIdx.x * blockDim.x + threadIdx.x;
    if (i >= TOT) return;
    int src, dst;
    if (i < EE) { src = ei[i]; dst = ei[EE + i]; }
    else        { src = i - EE; dst = src; }
    int p = atomicAdd(&g_cursor[g][dst], 1);
    g_csr[g][p] = src;
}

// ---------------- GEMM: O[M,128] = X[M,128] @ W[128,128]  (3xTF32 tensor) ----------------
// Block tile: 128(M) x 128(N), K chunked by 16. 8 warps in 4(M) x 2(N), each warp
// 32x64 via 2x8 m16n8k8 tiles. X/W pre-split into tf32 hi+lo in smem.
#define XS_STRIDE 20
#define WS_STRIDE 136
__global__ __launch_bounds__(256) void gemm_kernel(const float* __restrict__ X,
                                                   const float* __restrict__ W,
                                                   float* __restrict__ O) {
    __shared__ uint32_t XsH[128 * XS_STRIDE];    // 10.24 KB
    __shared__ uint32_t XsL[128 * XS_STRIDE];
    __shared__ uint32_t WsH[16 * WS_STRIDE];     // 8.7 KB
    __shared__ uint32_t WsL[16 * WS_STRIDE];

    const int t    = threadIdx.x;
    const int lane = t & 31;
    const int wid  = t >> 5;
    const int warpM = wid >> 1;                  // 0..3
    const int warpN = wid & 1;                   // 0..1
    const int m0 = warpM * 32;
    const int n0 = warpN * 64;
    const int g  = lane >> 2;                    // 0..7
    const int tg = lane & 3;                     // 0..3
    const int row0 = blockIdx.x * 128;

    float acc[2][8][4];
#pragma unroll
    for (int mt = 0; mt < 2; mt++)
#pragma unroll
        for (int nt = 0; nt < 8; nt++)
#pragma unroll
            for (int j = 0; j < 4; j++) acc[mt][nt][j] = 0.f;

    for (int kc = 0; kc < 128; kc += 16) {
        __syncthreads();
        // stage X tile [128 rows x 16 k] : 512 float4
#pragma unroll
        for (int i = t; i < 512; i += 256) {
            int r  = i >> 2;
            int kq = i & 3;
            int row = row0 + r; if (row >= NN) row = NN - 1;
            float4 v = *(const float4*)(X + (size_t)row * 128 + kc + kq * 4);
            uint32_t* ph = &XsH[r * XS_STRIDE + kq * 4];
            uint32_t* pl = &XsL[r * XS_STRIDE + kq * 4];
            float f[4] = {v.x, v.y, v.z, v.w};
#pragma unroll
            for (int j = 0; j < 4; j++) {
                uint32_t hb = to_tf32(f[j]);
                float lo = f[j] - __uint_as_float(hb);
                ph[j] = hb;
                pl[j] = to_tf32(lo);
            }
        }
        // stage W tile [16 k x 128 n] : 512 float4
#pragma unroll
        for (int i = t; i < 512; i += 256) {
            int kr = i >> 5;
            int c4 = i & 31;
            float4 v = *(const float4*)(W + (size_t)(kc + kr) * 128 + c4 * 4);
            uint32_t* ph = &WsH[kr * WS_STRIDE + c4 * 4];
            uint32_t* pl = &WsL[kr * WS_STRIDE + c4 * 4];
            float f[4] = {v.x, v.y, v.z, v.w};
#pragma unroll
            for (int j = 0; j < 4; j++) {
                uint32_t hb = to_tf32(f[j]);
                float lo = f[j] - __uint_as_float(hb);
                ph[j] = hb;
                pl[j] = to_tf32(lo);
            }
        }
        __syncthreads();

#pragma unroll
        for (int s = 0; s < 2; s++) {
            const int k0 = s * 8;
            uint32_t ah[2][4], al[2][4];
#pragma unroll
            for (int mt = 0; mt < 2; mt++) {
                int mr = m0 + mt * 16;
                ah[mt][0] = XsH[(mr + g)     * XS_STRIDE + k0 + tg];
                ah[mt][1] = XsH[(mr + g + 8) * XS_STRIDE + k0 + tg];
                ah[mt][2] = XsH[(mr + g)     * XS_STRIDE + k0 + tg + 4];
                ah[mt][3] = XsH[(mr + g + 8) * XS_STRIDE + k0 + tg + 4];
                al[mt][0] = XsL[(mr + g)     * XS_STRIDE + k0 + tg];
                al[mt][1] = XsL[(mr + g + 8) * XS_STRIDE + k0 + tg];
                al[mt][2] = XsL[(mr + g)     * XS_STRIDE + k0 + tg + 4];
                al[mt][3] = XsL[(mr + g + 8) * XS_STRIDE + k0 + tg + 4];
            }
#pragma unroll
            for (int nt = 0; nt < 8; nt++) {
                const int nc = n0 + nt * 8 + g;
                uint32_t bh[2], bl[2];
                bh[0] = WsH[(k0 + tg)     * WS_STRIDE + nc];
                bh[1] = WsH[(k0 + tg + 4) * WS_STRIDE + nc];
                bl[0] = WsL[(k0 + tg)     * WS_STRIDE + nc];
                bl[1] = WsL[(k0 + tg + 4) * WS_STRIDE + nc];
#pragma unroll
                for (int mt = 0; mt < 2; mt++) {
                    mma_tf32(acc[mt][nt], ah[mt], bh);
                    mma_tf32(acc[mt][nt], al[mt], bh);
                    mma_tf32(acc[mt][nt], ah[mt], bl);
                }
            }
        }
    }

    // epilogue: direct global stores
#pragma unroll
    for (int mt = 0; mt < 2; mt++) {
        int rowA = row0 + m0 + mt * 16 + g;
        int rowB = rowA + 8;
#pragma unroll
        for (int nt = 0; nt < 8; nt++) {
            int col = n0 + nt * 8 + tg * 2;
            if (rowA < NN)
                *(float2*)(O + (size_t)rowA * 128 + col) =
                    make_float2(acc[mt][nt][0], acc[mt][nt][1]);
            if (rowB < NN)
                *(float2*)(O + (size_t)rowB * 128 + col) =
                    make_float2(acc[mt][nt][2], acc[mt][nt][3]);
        }
    }
}

// ---------------- alpha_src / alpha_dst: per node per head dot products ----------------
__global__ void alpha_kernel(const float* __restrict__ H, int g,
                             const float* __restrict__ a_src,
                             const float* __restrict__ a_dst) {
    int w = (blockIdx.x * blockDim.x + threadIdx.x) >> 5;
    if (w >= NN) return;
    int lane = threadIdx.x & 31;
    int head = lane >> 4;
    int d0 = (lane & 15) * 4;
    float4 v = *(const float4*)(H + (size_t)w * 128 + lane * 4);
    const float* as = a_src + head * 64 + d0;
    const float* ad = a_dst + head * 64 + d0;
    float s = v.x * as[0] + v.y * as[1] + v.z * as[2] + v.w * as[3];
    float d = v.x * ad[0] + v.y * ad[1] + v.z * ad[2] + v.w * ad[3];
#pragma unroll
    for (int off = 8; off >= 1; off >>= 1) {
        s += __shfl_xor_sync(0xffffffffu, s, off);
        d += __shfl_xor_sync(0xffffffffu, d, off);
    }
    if ((lane & 15) == 0) {
        g_as[g][w * 2 + head] = s;
        g_ad[g][w * 2 + head] = d;
    }
}

// ---------------- softmax aggregation: one warp per destination node ----------------
__global__ void agg_kernel(const float* __restrict__ H, int g,
                           const float* __restrict__ bias,
                           float* __restrict__ out, int do_relu) {
    int w = (blockIdx.x * blockDim.x + threadIdx.x) >> 5;
    if (w >= NN) return;
    int lane = threadIdx.x & 31;
    int beg = g_rowstart[g][w], end = g_rowstart[g][w + 1];
    float ad0 = g_ad[g][w * 2], ad1 = g_ad[g][w * 2 + 1];

    // online softmax stats (m, s) per head
    float m0 = -1e30f, m1 = -1e30f, s0 = 0.f, s1 = 0.f;
    for (int e = beg + lane; e < end; e += 32) {
        int src = g_csr[g][e];
        float2 av = *(const float2*)&g_as[g][src * 2];
        float e0 = lrelu(av.x + ad0, 0.2f);
        float e1 = lrelu(av.y + ad1, 0.2f);
        if (e0 > m0) { s0 = s0 * __expf(m0 - e0) + 1.f; m0 = e0; } else s0 += __expf(e0 - m0);
        if (e1 > m1) { s1 = s1 * __expf(m1 - e1) + 1.f; m1 = e1; } else s1 += __expf(e1 - m1);
    }
#pragma unroll
    for (int off = 16; off >= 1; off >>= 1) {
        float mo = __shfl_xor_sync(0xffffffffu, m0, off);
        float so = __shfl_xor_sync(0xffffffffu, s0, off);
        float mn = fmaxf(m0, mo);
        s0 = s0 * __expf(m0 - mn) + so * __expf(mo - mn); m0 = mn;
        mo = __shfl_xor_sync(0xffffffffu, m1, off);
        so = __shfl_xor_sync(0xffffffffu, s1, off);
        mn = fmaxf(m1, mo);
        s1 = s1 * __expf(m1 - mn) + so * __expf(mo - mn); m1 = mn;
    }
    float inv0 = 1.f / s0;
    float inv1 = 1.f / s1;

    const int col  = lane * 4;
    const int head = lane >> 4;
    float4 acc = make_float4(0.f, 0.f, 0.f, 0.f);

    for (int base = beg; base < end; base += 32) {
        int cnt = end - base; if (cnt > 32) cnt = 32;
        int   sidx = 0; float aa0 = 0.f, aa1 = 0.f;
        if (lane < cnt) {
            sidx = g_csr[g][base + lane];
            float2 av = *(const float2*)&g_as[g][sidx * 2];
            float e0 = lrelu(av.x + ad0, 0.2f);
            float e1 = lrelu(av.y + ad1, 0.2f);
            aa0 = __expf(e0 - m0) * inv0;
            aa1 = __expf(e1 - m1) * inv1;
        }
#pragma unroll 4
        for (int j = 0; j < cnt; j++) {
            int   sj  = __shfl_sync(0xffffffffu, sidx, j);
            float a0j = __shfl_sync(0xffffffffu, aa0, j);
            float a1j = __shfl_sync(0xffffffffu, aa1, j);
            float aj  = head ? a1j : a0j;
            float4 v = *(const float4*)(H + (size_t)sj * 128 + col);
            acc.x += aj * v.x; acc.y += aj * v.y; acc.z += aj * v.z; acc.w += aj * v.w;
        }
    }

    float4 bv = *(const float4*)(bias + col);
    float4 r = make_float4(acc.x + bv.x, acc.y + bv.y, acc.z + bv.z, acc.w + bv.w);
    if (do_relu) {
        r.x = fmaxf(r.x, 0.f); r.y = fmaxf(r.y, 0.f);
        r.z = fmaxf(r.z, 0.f); r.w = fmaxf(r.w, 0.f);
    }
    *(float4*)(out + (size_t)w * 128 + col) = r;
}

// ---------------- tprob = leaky_relu(xZ2 @ Wp + bp, 0.01) ----------------
__global__ void tprob_kernel(const float* __restrict__ Z, const float* __restrict__ Wp,
                             const float* __restrict__ bp, float* __restrict__ out) {
    int w = (blockIdx.x * blockDim.x + threadIdx.x) >> 5;
    if (w >= NN) return;
    int lane = threadIdx.x & 31;
    int col = lane * 4;
    float4 v  = *(const float4*)(Z + (size_t)w * 128 + col);
    float4 p0 = *(const float4*)(Wp + col * 2);
    float4 p1 = *(const float4*)(Wp + col * 2 + 4);
    float a0 = v.x * p0.x + v.y * p0.z + v.z * p1.x + v.w * p1.z;
    float a1 = v.x * p0.y + v.y * p0.w + v.z * p1.y + v.w * p1.w;
#pragma unroll
    for (int off = 16; off >= 1; off >>= 1) {
        a0 += __shfl_xor_sync(0xffffffffu, a0, off);
        a1 += __shfl_xor_sync(0xffffffffu, a1, off);
    }
    if (lane == 0) {
        float o0 = lrelu(a0 + bp[0], 0.01f);
        float o1 = lrelu(a1 + bp[1], 0.01f);
        *(float2*)(out + (size_t)w * 2) = make_float2(o0, o1);
    }
}

// ---------------- fused y heads: blockIdx.y picks one of 4 (Z, idx, Wy) combos ----------------
__global__ void heads_kernel(const float* __restrict__ Z0, const float* __restrict__ Z1,
                             const int* __restrict__ treat, const int* __restrict__ control,
                             const float* __restrict__ WyS, const float* __restrict__ byS,
                             const float* __restrict__ Wy1, const float* __restrict__ by1,
                             const float* __restrict__ Wy0, const float* __restrict__ by0,
                             float* __restrict__ out, int nt, int nc) {
    __shared__ float Ws[128 * 64];
    __shared__ float bs[64];
    __shared__ float wy[64];
    __shared__ float byv;

    const int y = blockIdx.y;
    const float* Z   = (y == 0 || y == 2) ? Z0 : Z1;
    const int*   idx = (y < 2) ? treat : control;
    const float* Wy  = (y == 0 || y == 3) ? Wy1 : Wy0;
    const float* by  = (y == 0 || y == 3) ? by1 : by0;
    const int    cnt = (y < 2) ? nt : nc;
    float* yout = out + (y == 0 ? 0 : y == 1 ? nt : y == 2 ? 2 * nt : 2 * nt + nc);

    const int t = threadIdx.x;                   // 256 threads = 8 warps
#pragma unroll
    for (int i = 0; i < 32; i++) Ws[t + i * 256] = WyS[t + i * 256];
    if (t < 64) { bs[t] = byS[t]; wy[t] = Wy[t]; }
    if (t == 0) byv = by[0];
    __syncthreads();

    const int warp = t >> 5, lane = t & 31;
    for (int i = blockIdx.x * 8 + warp; i < cnt; i += gridDim.x * 8) {
        int node = idx[i];
        const float* z = Z + (size_t)node * 128;
        float za = z[lane], zb = z[lane + 32], zc = z[lane + 64], zd = z[lane + 96];
        float s0 = bs[lane], s1 = bs[lane + 32];
#pragma unroll
        for (int k = 0; k < 128; k++) {
            float src = (k < 32) ? za : (k < 64) ? zb : (k < 96) ? zc : zd;
            float zk = __shfl_sync(0xffffffffu, src, k & 31);
            s0 += zk * Ws[k * 64 + lane];
            s1 += zk * Ws[k * 64 + lane + 32];
        }
        s0 = lrelu(s0, 0.01f);
        s1 = lrelu(s1, 0.01f);
        float p = s0 * wy[lane] + s1 * wy[lane + 32];
#pragma unroll
        for (int off = 16; off >= 1; off >>= 1) p += __shfl_xor_sync(0xffffffffu, p, off);
        if (lane == 0) yout[i] = lrelu(p + byv, 0.01f);
    }
}

// ---------------- launch ----------------
static void build_csr(cudaStream_t s, const int* ei, int g, int* counts_ptr) {
    cudaMemsetAsync(counts_ptr, 0, NN * sizeof(int), s);
    hist_kernel<<<(EE + 255) / 256, 256, 0, s>>>(ei, g);
    scan_kernel<<<1, 1024, 0, s>>>(g);
    scatter_kernel<<<(TOT + 255) / 256, 256, 0, s>>>(ei, g);
}

static void run_conv(cudaStream_t s, const float* Xin, const float* W,
                     const float* asrc, const float* adst,
                     const float* bias, int g, float* outp, int do_relu, float* hbuf) {
    gemm_kernel<<<(NN + 127) / 128, 256, 0, s>>>(Xin, W, hbuf);
    alpha_kernel<<<(NN * 32) / 256, 256, 0, s>>>(hbuf, g, asrc, adst);
    agg_kernel<<<(NN * 32) / 256, 256, 0, s>>>(hbuf, g, bias, outp, do_relu);
}

extern "C" void kernel_launch(void* const* d_in, const int* in_sizes, int n_in,
                              void* d_out, int out_size) {
    const float* x       = (const float*)d_in[0];
    const int*   ei      = (const int*)d_in[1];
    const float* fx      = (const float*)d_in[2];
    const int*   fei     = (const int*)d_in[3];
    const int*   treat   = (const int*)d_in[4];
    const int*   control = (const int*)d_in[5];
    const float* W1      = (const float*)d_in[6];
    const float* as1     = (const float*)d_in[7];
    const float* ad1     = (const float*)d_in[8];
    const float* b1      = (const float*)d_in[9];
    const float* W2      = (const float*)d_in[10];
    const float* as2     = (const float*)d_in[11];
    const float* ad2     = (const float*)d_in[12];
    const float* b2      = (const float*)d_in[13];
    const float* WyS     = (const float*)d_in[14];
    const float* byS     = (const float*)d_in[15];
    const float* Wy1     = (const float*)d_in[16];
    const float* by1     = (const float*)d_in[17];
    const float* Wy0     = (const float*)d_in[18];
    const float* by0     = (const float*)d_in[19];
    const float* Wp      = (const float*)d_in[20];
    const float* bp      = (const float*)d_in[21];
    float* out = (float*)d_out;
    const int nt = in_sizes[4];
    const int nc = in_sizes[5];

    float* hbase  = nullptr;
    float* z1     = nullptr;
    int*   counts = nullptr;
    cudaGetSymbolAddress((void**)&hbase, g_h);
    cudaGetSymbolAddress((void**)&z1, g_z1);
    cudaGetSymbolAddress((void**)&counts, g_counts);
    float* hA  = hbase;
    float* hB  = hbase + (size_t)NN * 128;
    float* z1a = z1;
    float* z1b = z1 + (size_t)NN * 128;
    int* cntA = counts;
    int* cntB = counts + NN;

    const size_t OFF_XZ2  = (size_t)2 * nt + (size_t)2 * nc;
    const size_t OFF_XFZ2 = OFF_XZ2 + (size_t)NN * 128;
    const size_t OFF_TP   = OFF_XFZ2 + (size_t)NN * 128;

    // side stream + fork/join events (created once; host-side only, no device mem)
    static cudaStream_t sB = nullptr;
    static cudaEvent_t evFork = nullptr, evJoin = nullptr;
    if (sB == nullptr) {
        cudaStreamCreateWithFlags(&sB, cudaStreamNonBlocking);
        cudaEventCreateWithFlags(&evFork, cudaEventDisableTiming);
        cudaEventCreateWithFlags(&evJoin, cudaEventDisableTiming);
    }
    cudaStream_t sA = 0;  // legacy default (the captured stream)

    // fork
    cudaEventRecord(evFork, sA);
    cudaStreamWaitEvent(sB, evFork, 0);

    // real chain on sA
    build_csr(sA, ei, 0, cntA);
    run_conv(sA, x,   W1, as1, ad1, b1, 0, z1a, 1, hA);
    run_conv(sA, z1a, W2, as2, ad2, b2, 0, out + OFF_XZ2,  0, hA);
    tprob_kernel<<<(NN * 32) / 256, 256, 0, sA>>>(out + OFF_XZ2, Wp, bp, out + OFF_TP);

    // fake chain on sB
    build_csr(sB, fei, 1, cntB);
    run_conv(sB, fx,  W1, as1, ad1, b1, 1, z1b, 1, hB);
    run_conv(sB, z1b, W2, as2, ad2, b2, 1, out + OFF_XFZ2, 0, hB);

    // join
    cudaEventRecord(evJoin, sB);
    cudaStreamWaitEvent(sA, evJoin, 0);

    heads_kernel<<<dim3(32, 4), 256, 0, sA>>>(out + OFF_XZ2, out + OFF_XFZ2, treat, control,
                                              WyS, byS, Wy1, by1, Wy0, by0, out, nt, nc);
}